// round 1
// baseline (speedup 1.0000x reference)
#include <cuda_runtime.h>

#define BB 256
#define RR 1152
#define CC 10
#define OO 16
#define II 8
#define CO 160   // CC*OO
#define NITER 3

// Routing state (batch-shared) + intermediates. All reset/overwritten each launch.
__device__ float g_b[RR*CC];   // routing logits (11520)
__device__ float g_c[RR*CC];   // softmax couplings
__device__ float g_S[BB*CO];   // s_j (40960)
__device__ float g_V[BB*CO];   // v   (40960)

// ---------------------------------------------------------------------------
// init: zero logits, uniform couplings (softmax of zeros), zero S accumulator
// ---------------------------------------------------------------------------
__global__ void k_init() {
    int idx = blockIdx.x * blockDim.x + threadIdx.x;
    if (idx < RR*CC) { g_b[idx] = 0.0f; g_c[idx] = 1.0f / (float)RR; }
    if (idx < BB*CO) g_S[idx] = 0.0f;
}

// ---------------------------------------------------------------------------
// softmax over routes (axis r) per class c, and zero S for the next iteration
// ---------------------------------------------------------------------------
__global__ void k_softmax_zeroS() {
    int c = blockIdx.x;        // 0..9
    int t = threadIdx.x;       // 256 threads
    __shared__ float red[256];

    float m = -1e30f;
    for (int r = t; r < RR; r += 256) m = fmaxf(m, g_b[r*CC + c]);
    red[t] = m; __syncthreads();
    for (int s = 128; s > 0; s >>= 1) { if (t < s) red[t] = fmaxf(red[t], red[t+s]); __syncthreads(); }
    m = red[0]; __syncthreads();

    float sum = 0.0f;
    for (int r = t; r < RR; r += 256) sum += __expf(g_b[r*CC + c] - m);
    red[t] = sum; __syncthreads();
    for (int s = 128; s > 0; s >>= 1) { if (t < s) red[t] += red[t+s]; __syncthreads(); }
    float inv = 1.0f / red[0];

    for (int r = t; r < RR; r += 256) g_c[r*CC + c] = __expf(g_b[r*CC + c] - m) * inv;

    // zero this block's slice of S (40960/10 = 4096)
    for (int idx = c*4096 + t; idx < (c+1)*4096; idx += 256) g_S[idx] = 0.0f;
}

// ---------------------------------------------------------------------------
// s-partial: S[b,co] += sum over an r-chunk of c[r,c] * (W[r,co,:] . x[b,r,:])
// grid (72, 8): 72 r-chunks of 16, 8 b-tiles of 32. 256 threads.
// thread (tg = t>>5, bl = t&31): batch bl, outputs co in [tg*20, tg*20+20).
// ---------------------------------------------------------------------------
#define BT 32
#define RCH 16
__global__ void __launch_bounds__(256) k_spart(const float* __restrict__ x,
                                               const float* __restrict__ W) {
    __shared__ float sW[CO*II];    // 1280 floats: W[r] tile
    __shared__ float sX[BT*9];     // padded x tile (stride 9 -> conflict-free)
    __shared__ float sc[CC];       // couplings for this r

    int t  = threadIdx.x;
    int bl = t & 31;
    int tg = t >> 5;
    int r0 = blockIdx.x * RCH;
    int b0 = blockIdx.y * BT;
    int co0 = tg * 20;

    float acc[20];
    #pragma unroll
    for (int k = 0; k < 20; k++) acc[k] = 0.0f;

    for (int rl = 0; rl < RCH; rl++) {
        int r = r0 + rl;
        __syncthreads();
        // W[r]: 1280 floats = 320 float4 (cooperative)
        const float4* Wr = (const float4*)(W + (size_t)r * CO * II);
        float4* sW4 = (float4*)sW;
        sW4[t] = Wr[t];
        if (t < 64) sW4[256 + t] = Wr[256 + t];
        // x tile: 32 b x 8 i
        {
            int xb = t >> 3, xi = t & 7;
            sX[xb*9 + xi] = x[((size_t)(b0 + xb) * RR + r) * II + xi];
        }
        if (t < CC) sc[t] = g_c[r*CC + t];
        __syncthreads();

        float xr[8];
        #pragma unroll
        for (int i = 0; i < 8; i++) xr[i] = sX[bl*9 + i];

        #pragma unroll
        for (int k = 0; k < 20; k++) {
            int co = co0 + k;
            float4 w0 = ((const float4*)sW)[co*2];
            float4 w1 = ((const float4*)sW)[co*2 + 1];
            float u = w0.x*xr[0] + w0.y*xr[1] + w0.z*xr[2] + w0.w*xr[3]
                    + w1.x*xr[4] + w1.y*xr[5] + w1.z*xr[6] + w1.w*xr[7];
            acc[k] += sc[co >> 4] * u;
        }
    }

    #pragma unroll
    for (int k = 0; k < 20; k++)
        atomicAdd(&g_S[(size_t)(b0 + bl) * CO + co0 + k], acc[k]);
}

// ---------------------------------------------------------------------------
// squash: v = s*|s| / (1+s^2), optionally also write final output
// ---------------------------------------------------------------------------
__global__ void k_squash(float* __restrict__ out, int write_out) {
    int idx = blockIdx.x * blockDim.x + threadIdx.x;
    if (idx < BB*CO) {
        float s = g_S[idx];
        float v = s * fabsf(s) / (1.0f + s*s);
        g_V[idx] = v;
        if (write_out) out[idx] = v;
    }
}

// ---------------------------------------------------------------------------
// agreement + logit update:
//   G_r[i,co] = (1/B) sum_b x[b,r,i] * V[b,co]          (per-route 8x160 Gram)
//   b[r,c]   += sum_{o,i} W[r,c,o,i] * G_r[i, c*16+o]
// grid 144 blocks x 8 routes each, 256 threads.
// warp w <-> i = w; lane l owns co in {l, l+32, l+64, l+96, l+128}.
// ---------------------------------------------------------------------------
__global__ void __launch_bounds__(256) k_agree(const float* __restrict__ x,
                                               const float* __restrict__ W) {
    __shared__ float sbuf[10240];  // 40KB: x half-chunk (32KB) then Gram (40KB)
    int t = threadIdx.x;
    int w = t >> 5;    // i
    int l = t & 31;
    int r0 = blockIdx.x * 8;

    float acc[8][5];
    #pragma unroll
    for (int rl = 0; rl < 8; rl++)
        #pragma unroll
        for (int k = 0; k < 5; k++) acc[rl][k] = 0.0f;

    for (int half = 0; half < 2; half++) {
        int bbase = half * 128;
        __syncthreads();
        // stage x[bbase..bbase+128, r0..r0+8, :] -> sbuf[b*64 + rl*8 + i] (8192 floats)
        for (int idx = t; idx < 128*64; idx += 256) {
            int b    = idx >> 6;
            int rest = idx & 63;
            int rl   = rest >> 3, i = rest & 7;
            sbuf[idx] = x[((size_t)(bbase + b) * RR + r0 + rl) * II + i];
        }
        __syncthreads();

        // 1-ahead prefetch of V rows
        float vv[5];
        #pragma unroll
        for (int k = 0; k < 5; k++) vv[k] = g_V[(size_t)bbase * CO + l + 32*k];

        for (int b = 0; b < 128; b++) {
            float nv[5];
            if (b < 127) {
                #pragma unroll
                for (int k = 0; k < 5; k++)
                    nv[k] = g_V[(size_t)(bbase + b + 1) * CO + l + 32*k];
            }
            #pragma unroll
            for (int rl = 0; rl < 8; rl++) {
                float xv = sbuf[b*64 + rl*8 + w];
                #pragma unroll
                for (int k = 0; k < 5; k++) acc[rl][k] += xv * vv[k];
            }
            #pragma unroll
            for (int k = 0; k < 5; k++) vv[k] = nv[k];
        }
    }
    __syncthreads();

    // spill Gram to smem: sG[rl*1280 + i*160 + co]
    #pragma unroll
    for (int rl = 0; rl < 8; rl++)
        #pragma unroll
        for (int k = 0; k < 5; k++)
            sbuf[rl*1280 + w*160 + l + 32*k] = acc[rl][k];
    __syncthreads();

    // warp w handles route rl = w: a[r,c] = sum_{o,i} W[r,c,o,i]*G[i,c*16+o]
    int rl = w;
    int r  = r0 + rl;
    for (int c = 0; c < CC; c++) {
        const float4 w4 = *(const float4*)(W + ((size_t)r * CC + c) * OO * II + 4*l);
        float p = 0.0f;
        #pragma unroll
        for (int j = 0; j < 4; j++) {
            int idx = l*4 + j;          // idx = o*8 + i
            int o = idx >> 3, i = idx & 7;
            float wv = (j == 0) ? w4.x : (j == 1) ? w4.y : (j == 2) ? w4.z : w4.w;
            p += wv * sbuf[rl*1280 + i*160 + c*16 + o];
        }
        #pragma unroll
        for (int off = 16; off; off >>= 1)
            p += __shfl_xor_sync(0xffffffffu, p, off);
        if (l == 0) g_b[r*CC + c] += p * (1.0f / (float)BB);
    }
}

// ---------------------------------------------------------------------------
extern "C" void kernel_launch(void* const* d_in, const int* in_sizes, int n_in,
                              void* d_out, int out_size) {
    const float* x = (const float*)d_in[0];
    const float* W = (const float*)d_in[1];
    if (in_sizes[0] == RR*CC*OO*II && in_sizes[1] == BB*RR*II) {  // guard order
        W = (const float*)d_in[0];
        x = (const float*)d_in[1];
    }
    float* out = (float*)d_out;

    dim3 gS(RR/RCH, BB/BT);   // (72, 8)

    k_init<<<160, 256>>>();
    for (int it = 0; it < NITER; it++) {
        if (it > 0) k_softmax_zeroS<<<CC, 256>>>();
        k_spart<<<gS, 256>>>(x, W);
        k_squash<<<160, 256>>>(out, it == NITER - 1 ? 1 : 0);
        if (it < NITER - 1) k_agree<<<RR/8, 256>>>(x, W);
    }
}

// round 2
// speedup vs baseline: 1.4896x; 1.4896x over previous
#include <cuda_runtime.h>

#define BB 256
#define RR 1152
#define CC 10
#define OO 16
#define II 8
#define CO 160   // CC*OO
#define NITER 3

typedef unsigned long long ull;

// Routing state (batch-shared) + S accumulator. Reset every launch.
__device__ float g_b[RR*CC];   // routing logits
__device__ float g_c[RR*CC];   // softmax couplings
__device__ float g_S[BB*CO];   // s_j accumulator

// ---------------- f32x2 helpers (packed dual-FMA, sm_103a) ------------------
__device__ __forceinline__ ull ffma2(ull a, ull b, ull c) {
    ull d;
    asm("fma.rn.f32x2 %0, %1, %2, %3;" : "=l"(d) : "l"(a), "l"(b), "l"(c));
    return d;
}
__device__ __forceinline__ ull splat2(float x) {
    ull d;
    unsigned int u = __float_as_uint(x);
    asm("mov.b64 %0, {%1, %1};" : "=l"(d) : "r"(u));
    return d;
}
__device__ __forceinline__ void unpack2(ull a, float* lo, float* hi) {
    unsigned int l_, h_;
    asm("mov.b64 {%0, %1}, %2;" : "=r"(l_), "=r"(h_) : "l"(a));
    *lo = __uint_as_float(l_);
    *hi = __uint_as_float(h_);
}

// ---------------------------------------------------------------------------
// init: zero logits, uniform couplings, zero S
// ---------------------------------------------------------------------------
__global__ void k_init() {
    int idx = blockIdx.x * blockDim.x + threadIdx.x;
    if (idx < RR*CC) { g_b[idx] = 0.0f; g_c[idx] = 1.0f / (float)RR; }
    if (idx < BB*CO) g_S[idx] = 0.0f;
}

// ---------------------------------------------------------------------------
// softmax over routes per class + zero S for next iteration
// ---------------------------------------------------------------------------
__global__ void k_softmax_zeroS() {
    int c = blockIdx.x;
    int t = threadIdx.x;
    __shared__ float red[256];

    float m = -1e30f;
    for (int r = t; r < RR; r += 256) m = fmaxf(m, g_b[r*CC + c]);
    red[t] = m; __syncthreads();
    for (int s = 128; s > 0; s >>= 1) { if (t < s) red[t] = fmaxf(red[t], red[t+s]); __syncthreads(); }
    m = red[0]; __syncthreads();

    float sum = 0.0f;
    for (int r = t; r < RR; r += 256) sum += __expf(g_b[r*CC + c] - m);
    red[t] = sum; __syncthreads();
    for (int s = 128; s > 0; s >>= 1) { if (t < s) red[t] += red[t+s]; __syncthreads(); }
    float inv = 1.0f / red[0];

    for (int r = t; r < RR; r += 256) g_c[r*CC + c] = __expf(g_b[r*CC + c] - m) * inv;

    for (int idx = c*4096 + t; idx < (c+1)*4096; idx += 256) g_S[idx] = 0.0f;
}

// ---------------------------------------------------------------------------
// s-partial, f32x2 over batch pairs.
// grid (18, 4, 4): 18 r-chunks of 64, 4 b-tiles of 64, 4 co-groups of 40.
// thread (w=t>>5, l=t&31): co = co0 + w*5 + {0..4}; batches b0+2l, b0+2l+1.
// W staged pre-scaled by coupling and pre-splatted for f32x2 reads.
// Software-pipelined staging (prefetch rl+1 during compute of rl).
// ---------------------------------------------------------------------------
__global__ void __launch_bounds__(256) k_spart(const float* __restrict__ x,
                                               const float* __restrict__ W) {
    __shared__ __align__(16) float sW2[640];     // 40 co x 8 i x 2 (splatted Wc)
    __shared__ __align__(16) float sXt[8*66];    // [i][b] padded (stride 66)
    __shared__ float sC[64*10];                  // couplings for the r-chunk

    int t = threadIdx.x, w = t >> 5, l = t & 31;
    int r0  = blockIdx.x * 64;
    int b0  = blockIdx.y * 64;
    int co0 = blockIdx.z * 40;

    for (int idx = t; idx < 640; idx += 256)
        sC[idx] = g_c[(r0 + idx/10)*CC + idx%10];
    __syncthreads();   // sC ready

    int xi = t & 7, xb = t >> 3;
    size_t xbase0 = ((size_t)(b0 + xb) * RR) * II + xi;
    size_t xbase1 = ((size_t)(b0 + xb + 32) * RR) * II + xi;

    // prologue: prefetch rl = 0
    float px0 = x[xbase0 + (size_t)r0 * II];
    float px1 = x[xbase1 + (size_t)r0 * II];
    float4 pf = make_float4(0,0,0,0);
    float  pc = 0.0f;
    if (t < 160) {
        pf = ((const float4*)(W + ((size_t)r0 * CO + co0) * II))[t >> 1];
        pc = sC[0*10 + ((co0 + (t >> 2)) >> 4)];
    }

    ull acc[5];
    #pragma unroll
    for (int k = 0; k < 5; k++) acc[k] = 0ull;

    for (int rl = 0; rl < 64; rl++) {
        __syncthreads();   // previous compute done reading smem
        // store staged regs
        sXt[xi*66 + xb]      = px0;
        sXt[xi*66 + xb + 32] = px1;
        if (t < 160) {
            float4 d;
            if (t & 1) d = make_float4(pf.z*pc, pf.z*pc, pf.w*pc, pf.w*pc);
            else       d = make_float4(pf.x*pc, pf.x*pc, pf.y*pc, pf.y*pc);
            ((float4*)sW2)[t] = d;
        }
        // prefetch rl+1
        if (rl + 1 < 64) {
            int r = r0 + rl + 1;
            px0 = x[xbase0 + (size_t)r * II];
            px1 = x[xbase1 + (size_t)r * II];
            if (t < 160) {
                pf = ((const float4*)(W + ((size_t)r * CO + co0) * II))[t >> 1];
                pc = sC[(rl+1)*10 + ((co0 + (t >> 2)) >> 4)];
            }
        }
        __syncthreads();   // staged data visible

        ull xp[8];
        #pragma unroll
        for (int i = 0; i < 8; i++)
            xp[i] = *(const ull*)&sXt[i*66 + 2*l];

        #pragma unroll
        for (int k = 0; k < 5; k++) {
            const ull* wp = (const ull*)&sW2[(w*5 + k) * 16];
            ull a = acc[k];
            #pragma unroll
            for (int i = 0; i < 8; i++) a = ffma2(wp[i], xp[i], a);
            acc[k] = a;
        }
    }

    #pragma unroll
    for (int k = 0; k < 5; k++) {
        float lo, hi;
        unpack2(acc[k], &lo, &hi);
        int co = co0 + w*5 + k;
        atomicAdd(&g_S[(size_t)(b0 + 2*l)     * CO + co], lo);
        atomicAdd(&g_S[(size_t)(b0 + 2*l + 1) * CO + co], hi);
    }
}

// ---------------------------------------------------------------------------
// agreement + logit update (squash fused into V staging).
// grid (144, 4): 8 routes per block, 64 batches per block.
// warp w <-> i; lane l <-> co in {l+32k}. rl packed in pairs via f32x2.
//   G_r[i,co] = sum_b x[b,r,i] * squash(S)[b,co]
//   b[r,c]   += (1/B) * sum_{o,i} W[r,c,o,i] * G_r[i, c*16+o]   (atomic)
// ---------------------------------------------------------------------------
__global__ void __launch_bounds__(256) k_agree(const float* __restrict__ x,
                                               const float* __restrict__ W) {
    __shared__ __align__(16) float buf[10496];   // 41 KB
    float* sX = buf;           // 4096: [b][i*8+rl]
    float* sV = buf + 4096;    // 5120: [bs][co], 32 batches per sub-pass

    int t = threadIdx.x, w = t >> 5, l = t & 31;
    int r0    = blockIdx.x * 8;
    int bbase = blockIdx.y * 64;

    // stage x once: [b][i*8+rl]
    for (int idx = t; idx < 4096; idx += 256) {
        int b = idx >> 6, rest = idx & 63, rl = rest >> 3, i = rest & 7;
        sX[b*64 + i*8 + rl] = x[((size_t)(bbase + b) * RR + r0 + rl) * II + i];
    }

    ull acc[4][5];
    #pragma unroll
    for (int rp = 0; rp < 4; rp++)
        #pragma unroll
        for (int k = 0; k < 5; k++) acc[rp][k] = 0ull;

    for (int sub = 0; sub < 2; sub++) {
        __syncthreads();
        // stage squash(S) for 32 batches
        #pragma unroll
        for (int q = 0; q < 20; q++) {
            int idx = q*256 + t;
            int bs = idx / 160, co = idx % 160;
            float s = g_S[(size_t)(bbase + sub*32 + bs) * CO + co];
            sV[idx] = s * fabsf(s) / (1.0f + s*s);
        }
        __syncthreads();

        for (int b = 0; b < 32; b++) {
            const float* xb = &sX[(sub*32 + b)*64 + w*8];  // broadcast reads
            ull xp0 = *(const ull*)(xb + 0);
            ull xp1 = *(const ull*)(xb + 2);
            ull xp2 = *(const ull*)(xb + 4);
            ull xp3 = *(const ull*)(xb + 6);
            #pragma unroll
            for (int k = 0; k < 5; k++) {
                ull v2 = splat2(sV[b*160 + l + 32*k]);     // conflict-free
                acc[0][k] = ffma2(xp0, v2, acc[0][k]);
                acc[1][k] = ffma2(xp1, v2, acc[1][k]);
                acc[2][k] = ffma2(xp2, v2, acc[2][k]);
                acc[3][k] = ffma2(xp3, v2, acc[3][k]);
            }
        }
    }
    __syncthreads();

    // spill Gram: buf[rl*1280 + i*160 + co]
    #pragma unroll
    for (int rp = 0; rp < 4; rp++)
        #pragma unroll
        for (int k = 0; k < 5; k++) {
            float lo, hi;
            unpack2(acc[rp][k], &lo, &hi);
            buf[(2*rp    )*1280 + w*160 + l + 32*k] = lo;
            buf[(2*rp + 1)*1280 + w*160 + l + 32*k] = hi;
        }
    __syncthreads();

    // warp w -> route r0+w: a[r,c] = sum_{o,i} W[r,c,o,i] * G[i, c*16+o]
    int r = r0 + w;
    const float* G = &buf[w*1280];
    for (int c = 0; c < CC; c++) {
        float4 w4 = *(const float4*)(W + ((size_t)r * CC + c) * OO * II + 4*l);
        int i0 = 4*l;
        float p = w4.x * G[((i0  ) & 7)*160 + c*16 + ((i0  ) >> 3)]
                + w4.y * G[((i0+1) & 7)*160 + c*16 + ((i0+1) >> 3)]
                + w4.z * G[((i0+2) & 7)*160 + c*16 + ((i0+2) >> 3)]
                + w4.w * G[((i0+3) & 7)*160 + c*16 + ((i0+3) >> 3)];
        #pragma unroll
        for (int off = 16; off; off >>= 1)
            p += __shfl_xor_sync(0xffffffffu, p, off);
        if (l == 0) atomicAdd(&g_b[r*CC + c], p * (1.0f / (float)BB));
    }
}

// ---------------------------------------------------------------------------
// final squash -> output (B, C, O, 1) contiguous
// ---------------------------------------------------------------------------
__global__ void k_squash_out(float* __restrict__ out) {
    int idx = blockIdx.x * blockDim.x + threadIdx.x;
    if (idx < BB*CO) {
        float s = g_S[idx];
        out[idx] = s * fabsf(s) / (1.0f + s*s);
    }
}

// ---------------------------------------------------------------------------
extern "C" void kernel_launch(void* const* d_in, const int* in_sizes, int n_in,
                              void* d_out, int out_size) {
    const float* x = (const float*)d_in[0];
    const float* W = (const float*)d_in[1];
    if (in_sizes[0] == RR*CC*OO*II && in_sizes[1] == BB*RR*II) {  // guard order
        W = (const float*)d_in[0];
        x = (const float*)d_in[1];
    }
    float* out = (float*)d_out;

    k_init<<<160, 256>>>();
    for (int it = 0; it < NITER; it++) {
        k_spart<<<dim3(18, 4, 4), 256>>>(x, W);
        if (it < NITER - 1) {
            k_agree<<<dim3(144, 4), 256>>>(x, W);
            k_softmax_zeroS<<<CC, 256>>>();
        } else {
            k_squash_out<<<160, 256>>>(out);
        }
    }
}

// round 3
// speedup vs baseline: 1.6935x; 1.1369x over previous
#include <cuda_runtime.h>

#define BB 256
#define RR 1152
#define CC 10
#define OO 16
#define II 8
#define CO 160            // CC*OO
#define KK (RR*II)        // 9216
#define NITER 3

typedef unsigned long long ull;

__device__ float g_xT[KK*BB];   // x transposed: [k][b], 9.4 MB
__device__ float g_b[CC*RR];    // logits, [c][r]
__device__ float g_c[CC*RR];    // couplings, [c][r]
__device__ float g_S[BB*CO];    // s accumulator [b][co]

// ---------------- f32x2 helpers --------------------------------------------
__device__ __forceinline__ ull ffma2(ull a, ull b, ull c) {
    ull d;
    asm("fma.rn.f32x2 %0, %1, %2, %3;" : "=l"(d) : "l"(a), "l"(b), "l"(c));
    return d;
}
__device__ __forceinline__ ull splat2(float x) {
    ull d; unsigned u = __float_as_uint(x);
    asm("mov.b64 %0, {%1, %1};" : "=l"(d) : "r"(u));
    return d;
}
__device__ __forceinline__ void unpack2(ull a, float* lo, float* hi) {
    unsigned l_, h_;
    asm("mov.b64 {%0, %1}, %2;" : "=r"(l_), "=r"(h_) : "l"(a));
    *lo = __uint_as_float(l_); *hi = __uint_as_float(h_);
}

// ---------------------------------------------------------------------------
// prep: transpose x[b][k] -> xT[k][b] (smem-tiled) + init b/c/S
// grid (144, 4), 256 threads. k-tile 64, b-tile 64.
// ---------------------------------------------------------------------------
__global__ void __launch_bounds__(256) k_prep(const float* __restrict__ x) {
    __shared__ float tile[64][66];
    int t = threadIdx.x;
    int k0 = blockIdx.x * 64, b0 = blockIdx.y * 64;

    #pragma unroll
    for (int j = 0; j < 4; j++) {
        int idx = t + j*256;              // 1024 f4 = 64b x 16
        int bb = idx >> 4, c4 = idx & 15;
        float4 v = *(const float4*)(x + (size_t)(b0+bb)*KK + k0 + c4*4);
        tile[c4*4+0][bb] = v.x; tile[c4*4+1][bb] = v.y;
        tile[c4*4+2][bb] = v.z; tile[c4*4+3][bb] = v.w;
    }
    __syncthreads();
    #pragma unroll
    for (int j = 0; j < 4; j++) {
        int idx = t + j*256;
        int kk = idx >> 4, b4 = idx & 15;
        float4 v;
        v.x = tile[kk][b4*4+0]; v.y = tile[kk][b4*4+1];
        v.z = tile[kk][b4*4+2]; v.w = tile[kk][b4*4+3];
        *(float4*)(g_xT + (size_t)(k0+kk)*BB + b0 + b4*4) = v;
    }

    // fused init (147456 threads cover everything once)
    int id = (blockIdx.y * 144 + blockIdx.x) * 256 + t;
    if (id < CC*RR) { g_b[id] = 0.0f; g_c[id] = 1.0f / (float)RR; }
    if (id < BB*CO) g_S[id] = 0.0f;
}

// ---------------------------------------------------------------------------
// s GEMM: S[b,co] += sum_k (c-scaled W)[k,co] * xT[k,b]
// grid (18 ks, 4 bt, 2 ct), 256 thr. Block tile 64b x 80co, K-chunk 512.
// thread: warp=co-strip(10 co = 5 pairs), lane=b-pair. 10 FFMA2 : 6 LDS per k.
// ---------------------------------------------------------------------------
__global__ void __launch_bounds__(256) k_spart(const float* __restrict__ W) {
    __shared__ float sX[32][64];     // xT tile (stage)
    __shared__ float sW[32][80];     // scaled W tile
    __shared__ float sc[64*5];       // couplings: [rl][class-local]

    int t = threadIdx.x;
    int cs = t >> 5, bg = t & 31;    // warp -> co strip, lane -> b pair
    int r0  = blockIdx.x * 64;       // k range [r0*8, r0*8+512)
    int b0  = blockIdx.y * 64;
    int co0 = blockIdx.z * 80;
    int cl0 = blockIdx.z * 5;        // class range

    // stage couplings for this r-chunk (320 floats)
    for (int idx = t; idx < 320; idx += 256) {
        int rl = idx / 5, cl = idx % 5;
        sc[idx] = g_c[(cl0 + cl)*RR + r0 + rl];
    }

    ull acc[2][5];
    #pragma unroll
    for (int b = 0; b < 2; b++)
        #pragma unroll
        for (int j = 0; j < 5; j++) acc[b][j] = 0ull;

    // staging register buffers
    float4 rx0, rx1, rw0, rw1, rw2;
    float  rs0, rs1, rs2;
    int wf0 = t, wf1 = t + 256, wf2 = t + 512;   // W f4 ids (640 total)

    __syncthreads();  // sc ready (needed by first stage scaling)

    // prologue: load stage 0
    {
        int k0 = r0*8;
        int kl0 = t >> 4, c40 = t & 15;
        rx0 = *(const float4*)(g_xT + (size_t)(k0 + kl0)*BB + b0 + c40*4);
        rx1 = *(const float4*)(g_xT + (size_t)(k0 + kl0 + 16)*BB + b0 + c40*4);
        {
            int f = wf0, rl = f/160, rem = f%160, coL = rem>>1, i0 = (rem&1)*4;
            rw0 = *(const float4*)(W + (size_t)(r0+rl)*CO*II + (co0+coL)*II + i0);
            rs0 = sc[rl*5 + (coL>>4)];
        }
        {
            int f = wf1, rl = f/160, rem = f%160, coL = rem>>1, i0 = (rem&1)*4;
            rw1 = *(const float4*)(W + (size_t)(r0+rl)*CO*II + (co0+coL)*II + i0);
            rs1 = sc[rl*5 + (coL>>4)];
        }
        if (t < 128) {
            int f = wf2, rl = f/160, rem = f%160, coL = rem>>1, i0 = (rem&1)*4;
            rw2 = *(const float4*)(W + (size_t)(r0+rl)*CO*II + (co0+coL)*II + i0);
            rs2 = sc[rl*5 + (coL>>4)];
        }
    }

    for (int s = 0; s < 16; s++) {
        __syncthreads();   // everyone done computing previous stage
        // commit staged regs to smem
        {
            int kl0 = t >> 4, c40 = t & 15;
            *(float4*)&sX[kl0][c40*4]      = rx0;
            *(float4*)&sX[kl0 + 16][c40*4] = rx1;
            int f = wf0, rl = f/160, rem = f%160, coL = rem>>1, i0 = (rem&1)*4;
            sW[rl*8+i0+0][coL] = rw0.x*rs0; sW[rl*8+i0+1][coL] = rw0.y*rs0;
            sW[rl*8+i0+2][coL] = rw0.z*rs0; sW[rl*8+i0+3][coL] = rw0.w*rs0;
            f = wf1; rl = f/160; rem = f%160; coL = rem>>1; i0 = (rem&1)*4;
            sW[rl*8+i0+0][coL] = rw1.x*rs1; sW[rl*8+i0+1][coL] = rw1.y*rs1;
            sW[rl*8+i0+2][coL] = rw1.z*rs1; sW[rl*8+i0+3][coL] = rw1.w*rs1;
            if (t < 128) {
                f = wf2; rl = f/160; rem = f%160; coL = rem>>1; i0 = (rem&1)*4;
                sW[rl*8+i0+0][coL] = rw2.x*rs2; sW[rl*8+i0+1][coL] = rw2.y*rs2;
                sW[rl*8+i0+2][coL] = rw2.z*rs2; sW[rl*8+i0+3][coL] = rw2.w*rs2;
            }
        }
        __syncthreads();   // stage visible

        // prefetch stage s+1
        if (s + 1 < 16) {
            int rbase = r0 + (s+1)*4;
            int k0 = rbase*8;
            int kl0 = t >> 4, c40 = t & 15;
            rx0 = *(const float4*)(g_xT + (size_t)(k0 + kl0)*BB + b0 + c40*4);
            rx1 = *(const float4*)(g_xT + (size_t)(k0 + kl0 + 16)*BB + b0 + c40*4);
            {
                int f = wf0, rl = f/160, rem = f%160, coL = rem>>1, i0 = (rem&1)*4;
                rw0 = *(const float4*)(W + (size_t)(rbase+rl)*CO*II + (co0+coL)*II + i0);
                rs0 = sc[((s+1)*4+rl)*5 + (coL>>4)];
            }
            {
                int f = wf1, rl = f/160, rem = f%160, coL = rem>>1, i0 = (rem&1)*4;
                rw1 = *(const float4*)(W + (size_t)(rbase+rl)*CO*II + (co0+coL)*II + i0);
                rs1 = sc[((s+1)*4+rl)*5 + (coL>>4)];
            }
            if (t < 128) {
                int f = wf2, rl = f/160, rem = f%160, coL = rem>>1, i0 = (rem&1)*4;
                rw2 = *(const float4*)(W + (size_t)(rbase+rl)*CO*II + (co0+coL)*II + i0);
                rs2 = sc[((s+1)*4+rl)*5 + (coL>>4)];
            }
        }

        // compute 32 k-steps
        #pragma unroll 4
        for (int kl = 0; kl < 32; kl++) {
            ull xp = *(const ull*)&sX[kl][2*bg];
            float x0, x1; unpack2(xp, &x0, &x1);
            ull x00 = splat2(x0), x11 = splat2(x1);
            const ull* wp = (const ull*)&sW[kl][cs*10];
            #pragma unroll
            for (int j = 0; j < 5; j++) {
                ull w2 = wp[j];
                acc[0][j] = ffma2(w2, x00, acc[0][j]);
                acc[1][j] = ffma2(w2, x11, acc[1][j]);
            }
        }
    }

    // atomic tail: 20 adds
    #pragma unroll
    for (int b = 0; b < 2; b++) {
        int gb = b0 + 2*bg + b;
        #pragma unroll
        for (int j = 0; j < 5; j++) {
            float lo, hi; unpack2(acc[b][j], &lo, &hi);
            atomicAdd(&g_S[(size_t)gb*CO + co0 + cs*10 + 2*j],     lo);
            atomicAdd(&g_S[(size_t)gb*CO + co0 + cs*10 + 2*j + 1], hi);
        }
    }
}

// ---------------------------------------------------------------------------
// agree: G[k,co] = sum_b xT[k,b]*squash(S)[b,co]; then contract with W into
// logits. grid 144 (8 routes = 64 k each), 512 threads, no atomics on G.
// ---------------------------------------------------------------------------
__global__ void __launch_bounds__(512) k_agree(const float* __restrict__ W) {
    __shared__ float sm[64*162];        // 41.5 KB; staged region reused by sG
    float* sV  = sm;                    // [32][160]   (5120)
    float* sXa = sm + 5120;             // [32][66]    (2112)

    int t = threadIdx.x, w = t >> 5, l = t & 31;
    int r0 = blockIdx.x * 8;
    int k0 = r0 * 8;

    ull acc[2][5];
    #pragma unroll
    for (int kk = 0; kk < 2; kk++)
        #pragma unroll
        for (int j = 0; j < 5; j++) acc[kk][j] = 0ull;

    for (int sub = 0; sub < 8; sub++) {
        int bs0 = sub * 32;
        __syncthreads();
        // stage squash(S): 1280 f4
        #pragma unroll
        for (int q = 0; q < 3; q++) {
            int idx = t + q*512;
            if (idx < 1280) {
                int bsl = idx / 40, c4 = idx % 40;
                float4 v = *(const float4*)(g_S + (size_t)(bs0+bsl)*CO + c4*4);
                v.x = v.x * fabsf(v.x) / (1.0f + v.x*v.x);
                v.y = v.y * fabsf(v.y) / (1.0f + v.y*v.y);
                v.z = v.z * fabsf(v.z) / (1.0f + v.z*v.z);
                v.w = v.w * fabsf(v.w) / (1.0f + v.w*v.w);
                *(float4*)&sV[bsl*160 + c4*4] = v;
            }
        }
        // stage xT chunk: 64 k x 32 b -> sXa[b][k]
        {
            int kl = t >> 3, b4 = t & 7;
            float4 v = *(const float4*)(g_xT + (size_t)(k0+kl)*BB + bs0 + b4*4);
            sXa[(b4*4+0)*66 + kl] = v.x; sXa[(b4*4+1)*66 + kl] = v.y;
            sXa[(b4*4+2)*66 + kl] = v.z; sXa[(b4*4+3)*66 + kl] = v.w;
        }
        __syncthreads();

        #pragma unroll 2
        for (int b = 0; b < 32; b++) {
            ull xp = *(const ull*)&sXa[b*66 + 2*l];
            float x0, x1; unpack2(xp, &x0, &x1);
            ull x00 = splat2(x0), x11 = splat2(x1);
            const ull* vp = (const ull*)&sV[b*160 + w*10];
            #pragma unroll
            for (int j = 0; j < 5; j++) {
                ull v2 = vp[j];
                acc[0][j] = ffma2(v2, x00, acc[0][j]);
                acc[1][j] = ffma2(v2, x11, acc[1][j]);
            }
        }
    }
    __syncthreads();

    // spill Gram: sG[k][co], stride 162
    #pragma unroll
    for (int kk = 0; kk < 2; kk++)
        #pragma unroll
        for (int j = 0; j < 5; j++)
            *(ull*)&sm[(2*l + kk)*162 + w*10 + 2*j] = acc[kk][j];
    __syncthreads();

    // contraction: warp pair per route; halves of classes
    int rl = w >> 1, ch = w & 1;
    int r = r0 + rl;
    #pragma unroll
    for (int cc = 0; cc < 5; cc++) {
        int c = ch*5 + cc;
        float4 w4 = *(const float4*)(W + ((size_t)r*CC + c)*OO*II + 4*l);
        int e0 = 4*l;
        float p = w4.x * sm[(rl*8 + ((e0  )&7))*162 + c*16 + ((e0  )>>3)]
                + w4.y * sm[(rl*8 + ((e0+1)&7))*162 + c*16 + ((e0+1)>>3)]
                + w4.z * sm[(rl*8 + ((e0+2)&7))*162 + c*16 + ((e0+2)>>3)]
                + w4.w * sm[(rl*8 + ((e0+3)&7))*162 + c*16 + ((e0+3)>>3)];
        #pragma unroll
        for (int off = 16; off; off >>= 1)
            p += __shfl_xor_sync(0xffffffffu, p, off);
        if (l == 0) g_b[c*RR + r] += p * (1.0f / (float)BB);
    }
}

// ---------------------------------------------------------------------------
// softmax over routes per class (coalesced on [c][r] layout) + zero S
// ---------------------------------------------------------------------------
__global__ void __launch_bounds__(256) k_softmax_zeroS() {
    int c = blockIdx.x, t = threadIdx.x;
    __shared__ float red[8];

    float v[5];
    #pragma unroll
    for (int q = 0; q < 5; q++) {
        int r = t + q*256;
        v[q] = (r < RR) ? g_b[c*RR + r] : -1e30f;
    }
    float m = fmaxf(fmaxf(fmaxf(v[0], v[1]), fmaxf(v[2], v[3])), v[4]);
    #pragma unroll
    for (int off = 16; off; off >>= 1) m = fmaxf(m, __shfl_xor_sync(~0u, m, off));
    if ((t & 31) == 0) red[t >> 5] = m;
    __syncthreads();
    m = red[0];
    #pragma unroll
    for (int q = 1; q < 8; q++) m = fmaxf(m, red[q]);

    float e[5], sum = 0.0f;
    #pragma unroll
    for (int q = 0; q < 5; q++) {
        int r = t + q*256;
        e[q] = (r < RR) ? __expf(v[q] - m) : 0.0f;
        sum += e[q];
    }
    #pragma unroll
    for (int off = 16; off; off >>= 1) sum += __shfl_xor_sync(~0u, sum, off);
    __syncthreads();
    if ((t & 31) == 0) red[t >> 5] = sum;
    __syncthreads();
    sum = 0.0f;
    #pragma unroll
    for (int q = 0; q < 8; q++) sum += red[q];
    float inv = 1.0f / sum;

    #pragma unroll
    for (int q = 0; q < 5; q++) {
        int r = t + q*256;
        if (r < RR) g_c[c*RR + r] = e[q] * inv;
    }
    // zero this class's S slice (4096 floats = 1024 f4)
    float4 z = make_float4(0,0,0,0);
    #pragma unroll
    for (int q = 0; q < 4; q++)
        *(float4*)(g_S + c*4096 + (q*256 + t)*4) = z;
}

// ---------------------------------------------------------------------------
__global__ void k_squash_out(float* __restrict__ out) {
    int idx = blockIdx.x * blockDim.x + threadIdx.x;
    if (idx < BB*CO) {
        float s = g_S[idx];
        out[idx] = s * fabsf(s) / (1.0f + s*s);
    }
}

// ---------------------------------------------------------------------------
extern "C" void kernel_launch(void* const* d_in, const int* in_sizes, int n_in,
                              void* d_out, int out_size) {
    const float* x = (const float*)d_in[0];
    const float* W = (const float*)d_in[1];
    if (in_sizes[0] == RR*CC*OO*II && in_sizes[1] == BB*RR*II) {
        W = (const float*)d_in[0];
        x = (const float*)d_in[1];
    }
    float* out = (float*)d_out;

    k_prep<<<dim3(144, 4), 256>>>(x);
    for (int it = 0; it < NITER; it++) {
        k_spart<<<dim3(18, 4, 2), 256>>>(W);
        if (it < NITER - 1) {
            k_agree<<<144, 512>>>(W);
            k_softmax_zeroS<<<CC, 256>>>();
        } else {
            k_squash_out<<<160, 256>>>(out);
        }
    }
}

// round 4
// speedup vs baseline: 2.3955x; 1.4145x over previous
#include <cuda_runtime.h>

#define BB 256
#define RR 1152
#define CC 10
#define OO 16
#define II 8
#define CO 160            // CC*OO
#define KK (RR*II)        // 9216
#define NITER 3
#define KSPLIT 72         // k_spart: K chunks of 128 k (16 r)

typedef unsigned long long ull;

__device__ float g_xT[KK*BB];            // x transposed [k][b]
__device__ float g_b[CC*RR];             // logits [c][r]
__device__ float g_c[CC*RR];             // couplings [c][r]
__device__ float g_part[KSPLIT*BB*CO];   // split-K partials of S
__device__ float g_V[BB*CO];             // squashed v [b][co]

// ---------------- f32x2 helpers --------------------------------------------
__device__ __forceinline__ ull ffma2(ull a, ull b, ull c) {
    ull d;
    asm("fma.rn.f32x2 %0, %1, %2, %3;" : "=l"(d) : "l"(a), "l"(b), "l"(c));
    return d;
}
__device__ __forceinline__ ull splat2(float x) {
    ull d; unsigned u = __float_as_uint(x);
    asm("mov.b64 %0, {%1, %1};" : "=l"(d) : "r"(u));
    return d;
}
__device__ __forceinline__ void unpack2(ull a, float* lo, float* hi) {
    unsigned l_, h_;
    asm("mov.b64 {%0, %1}, %2;" : "=r"(l_), "=r"(h_) : "l"(a));
    *lo = __uint_as_float(l_); *hi = __uint_as_float(h_);
}
__device__ __forceinline__ float squashf(float s) {
    return s * fabsf(s) / (1.0f + s*s);
}

// ---------------------------------------------------------------------------
// prep: transpose x[b][k] -> xT[k][b] + init logits/couplings
// ---------------------------------------------------------------------------
__global__ void __launch_bounds__(256) k_prep(const float* __restrict__ x) {
    __shared__ float tile[64][66];
    int t = threadIdx.x;
    int k0 = blockIdx.x * 64, b0 = blockIdx.y * 64;

    #pragma unroll
    for (int j = 0; j < 4; j++) {
        int idx = t + j*256;
        int bb = idx >> 4, c4 = idx & 15;
        float4 v = *(const float4*)(x + (size_t)(b0+bb)*KK + k0 + c4*4);
        tile[c4*4+0][bb] = v.x; tile[c4*4+1][bb] = v.y;
        tile[c4*4+2][bb] = v.z; tile[c4*4+3][bb] = v.w;
    }
    __syncthreads();
    #pragma unroll
    for (int j = 0; j < 4; j++) {
        int idx = t + j*256;
        int kk = idx >> 4, b4 = idx & 15;
        float4 v;
        v.x = tile[kk][b4*4+0]; v.y = tile[kk][b4*4+1];
        v.z = tile[kk][b4*4+2]; v.w = tile[kk][b4*4+3];
        *(float4*)(g_xT + (size_t)(k0+kk)*BB + b0 + b4*4) = v;
    }
    int id = (blockIdx.y * 144 + blockIdx.x) * 256 + t;
    if (id < CC*RR) { g_b[id] = 0.0f; g_c[id] = 1.0f / (float)RR; }
}

// ---------------------------------------------------------------------------
// s GEMM partials: part[ks][b][co] = sum_{k in chunk} (c-scaled W)[k,co]*xT[k,b]
// grid (72, 2). Block tile 128b x 160co. 8 warps = (2 wb x 4 wc).
// lane (lb=l>>2, lc=l&3): tile 8b x 10co -> 40 FFMA2 per k-step.
// Double-buffered stages of 8 k (one r); single barrier per stage.
// ---------------------------------------------------------------------------
__global__ void __launch_bounds__(256) k_spart(const float* __restrict__ W) {
    __shared__ __align__(16) float sX[2][8][128];
    __shared__ __align__(16) float sW[2][8][160];
    __shared__ float sc[16*10];

    int t = threadIdx.x;
    int w = t >> 5, l = t & 31;
    int wb = w >> 2, wc = w & 3;
    int lb = l >> 2, lc = l & 3;
    int ks = blockIdx.x, bt = blockIdx.y;
    int r0 = ks * 16;
    int b0 = bt * 128;
    int xb0 = wb*64 + lb*8;
    int wc0 = wc*40 + lc*10;

    // couplings for the 16 r of this chunk: sc[rl*10 + class]
    if (t < 160) sc[t] = g_c[(t % 10)*RR + r0 + (t / 10)];

    // staging thread roles
    int kl = t >> 5, b4 = t & 31;      // x: f4 per thread
    float4 rx, rwa, rwb;
    float  rs = 0.0f;

    __syncthreads();   // sc ready

    // prologue: stage 0
    rx = *(const float4*)(g_xT + (size_t)((r0)*8 + kl)*BB + b0 + b4*4);
    if (t < 160) {
        const float* wp = W + ((size_t)r0*CO + t)*II;
        rwa = *(const float4*)(wp);
        rwb = *(const float4*)(wp + 4);
        rs  = sc[0*10 + (t >> 4)];
    }
    *(float4*)&sX[0][kl][b4*4] = rx;
    if (t < 160) {
        sW[0][0][t] = rwa.x*rs; sW[0][1][t] = rwa.y*rs;
        sW[0][2][t] = rwa.z*rs; sW[0][3][t] = rwa.w*rs;
        sW[0][4][t] = rwb.x*rs; sW[0][5][t] = rwb.y*rs;
        sW[0][6][t] = rwb.z*rs; sW[0][7][t] = rwb.w*rs;
    }

    ull acc[8][5];
    #pragma unroll
    for (int bi = 0; bi < 8; bi++)
        #pragma unroll
        for (int j = 0; j < 5; j++) acc[bi][j] = 0ull;

    for (int s = 0; s < 16; s++) {
        int p = s & 1;
        if (s < 15) {   // prefetch stage s+1 into regs
            int r = r0 + s + 1;
            rx = *(const float4*)(g_xT + (size_t)(r*8 + kl)*BB + b0 + b4*4);
            if (t < 160) {
                const float* wp = W + ((size_t)r*CO + t)*II;
                rwa = *(const float4*)(wp);
                rwb = *(const float4*)(wp + 4);
                rs  = sc[(s+1)*10 + (t >> 4)];
            }
        }
        __syncthreads();   // stage s visible; stage s+1 buffer free

        #pragma unroll
        for (int kk = 0; kk < 8; kk++) {
            float xv[8];
            *(float4*)&xv[0] = *(const float4*)&sX[p][kk][xb0];
            *(float4*)&xv[4] = *(const float4*)&sX[p][kk][xb0 + 4];
            ull wv[5];
            const float* wrow = &sW[p][kk][wc0];
            #pragma unroll
            for (int j = 0; j < 5; j++) wv[j] = *(const ull*)(wrow + 2*j);
            #pragma unroll
            for (int bi = 0; bi < 8; bi++) {
                ull xs = splat2(xv[bi]);
                #pragma unroll
                for (int j = 0; j < 5; j++)
                    acc[bi][j] = ffma2(wv[j], xs, acc[bi][j]);
            }
        }

        if (s < 15) {   // commit prefetched stage
            int q = (s + 1) & 1;
            *(float4*)&sX[q][kl][b4*4] = rx;
            if (t < 160) {
                sW[q][0][t] = rwa.x*rs; sW[q][1][t] = rwa.y*rs;
                sW[q][2][t] = rwa.z*rs; sW[q][3][t] = rwa.w*rs;
                sW[q][4][t] = rwb.x*rs; sW[q][5][t] = rwb.y*rs;
                sW[q][6][t] = rwb.z*rs; sW[q][7][t] = rwb.w*rs;
            }
        }
    }

    // write partials (no atomics)
    float* dst = g_part + (size_t)ks*BB*CO;
    #pragma unroll
    for (int bi = 0; bi < 8; bi++) {
        float* row = dst + (size_t)(b0 + xb0 + bi)*CO + wc0;
        #pragma unroll
        for (int j = 0; j < 5; j++) *(ull*)(row + 2*j) = acc[bi][j];
    }
}

// ---------------------------------------------------------------------------
// reduce split-K partials, squash -> g_V; also final output on last iter
// grid 40 x 256, one f4 per thread
// ---------------------------------------------------------------------------
__global__ void __launch_bounds__(256) k_sqreduce(float* __restrict__ out,
                                                  int write_out) {
    int idx4 = blockIdx.x * 256 + threadIdx.x;   // 0..10239
    float4 s = make_float4(0,0,0,0);
    #pragma unroll 8
    for (int p = 0; p < KSPLIT; p++) {
        float4 v = *(const float4*)(g_part + (size_t)p*BB*CO + (size_t)idx4*4);
        s.x += v.x; s.y += v.y; s.z += v.z; s.w += v.w;
    }
    float4 q;
    q.x = squashf(s.x); q.y = squashf(s.y); q.z = squashf(s.z); q.w = squashf(s.w);
    *(float4*)(g_V + (size_t)idx4*4) = q;
    if (write_out) *(float4*)(out + (size_t)idx4*4) = q;
}

// ---------------------------------------------------------------------------
// agree: G[k,co] = sum_b xT[k,b]*V[b,co], then contract with W into logits.
// grid 144 (64 k = 8 routes per CTA). 8 warps = (2 wk x 4 wc).
// lane (lk=l>>2, lc=l&3): tile 4k x 10co -> 20 FFMA2 per b-step.
// ---------------------------------------------------------------------------
__global__ void __launch_bounds__(256) k_agree(const float* __restrict__ W) {
    __shared__ __align__(16) float sm[64*162];   // 41.5 KB (reused as sG)
    float* sV  = sm;          // [32][160] = 5120
    float* sXa = sm + 5120;   // [32][68]  = 2176

    int t = threadIdx.x;
    int w = t >> 5, l = t & 31;
    int wk = w >> 2, wc = w & 3;
    int lk = l >> 2, lc = l & 3;
    int r0 = blockIdx.x * 8;
    int k0 = r0 * 8;
    int klq = wk*32 + lk*4;        // local k base for this lane
    int wc0 = wc*40 + lc*10;

    ull acc[4][5];
    #pragma unroll
    for (int ki = 0; ki < 4; ki++)
        #pragma unroll
        for (int j = 0; j < 5; j++) acc[ki][j] = 0ull;

    for (int sub = 0; sub < 8; sub++) {
        int bs0 = sub * 32;
        __syncthreads();
        // stage V: 1280 f4, coalesced
        #pragma unroll
        for (int q = 0; q < 5; q++) {
            int idx = t + q*256;
            *(float4*)&sV[idx*4] =
                *(const float4*)(g_V + (size_t)bs0*CO + (size_t)idx*4);
        }
        // stage x transposed: 64k x 32b -> sXa[b][k] (stride 68)
        #pragma unroll
        for (int q = 0; q < 2; q++) {
            int idx = t + q*256;            // 0..511
            int kl = idx >> 3, bb = idx & 7;
            float4 v = *(const float4*)(g_xT + (size_t)(k0+kl)*BB + bs0 + bb*4);
            sXa[(bb*4+0)*68 + kl] = v.x; sXa[(bb*4+1)*68 + kl] = v.y;
            sXa[(bb*4+2)*68 + kl] = v.z; sXa[(bb*4+3)*68 + kl] = v.w;
        }
        __syncthreads();

        #pragma unroll 2
        for (int b = 0; b < 32; b++) {
            float4 xk = *(const float4*)&sXa[b*68 + klq];
            ull vv[5];
            const float* vrow = &sV[b*160 + wc0];
            #pragma unroll
            for (int j = 0; j < 5; j++) vv[j] = *(const ull*)(vrow + 2*j);
            ull xs0 = splat2(xk.x), xs1 = splat2(xk.y);
            ull xs2 = splat2(xk.z), xs3 = splat2(xk.w);
            #pragma unroll
            for (int j = 0; j < 5; j++) {
                acc[0][j] = ffma2(vv[j], xs0, acc[0][j]);
                acc[1][j] = ffma2(vv[j], xs1, acc[1][j]);
                acc[2][j] = ffma2(vv[j], xs2, acc[2][j]);
                acc[3][j] = ffma2(vv[j], xs3, acc[3][j]);
            }
        }
    }
    __syncthreads();

    // spill G to smem: sG[k][co], stride 162
    #pragma unroll
    for (int ki = 0; ki < 4; ki++)
        #pragma unroll
        for (int j = 0; j < 5; j++)
            *(ull*)&sm[(klq + ki)*162 + wc0 + 2*j] = acc[ki][j];
    __syncthreads();

    // contraction: warp w -> route r0+w. a[r,c] = sum_{o,i} W[r,c,o,i]*G[i,co]
    int r = r0 + w;
    const float* G = &sm[(w*8)*162];    // k local = w*8 + i
    for (int c = 0; c < CC; c++) {
        float4 w4 = *(const float4*)(W + ((size_t)r*CC + c)*OO*II + 4*l);
        int e0 = 4*l;
        float p = w4.x * G[((e0  )&7)*162 + c*16 + ((e0  )>>3)]
                + w4.y * G[((e0+1)&7)*162 + c*16 + ((e0+1)>>3)]
                + w4.z * G[((e0+2)&7)*162 + c*16 + ((e0+2)>>3)]
                + w4.w * G[((e0+3)&7)*162 + c*16 + ((e0+3)>>3)];
        #pragma unroll
        for (int off = 16; off; off >>= 1)
            p += __shfl_xor_sync(0xffffffffu, p, off);
        if (l == 0) g_b[c*RR + r] += p * (1.0f / (float)BB);
    }
}

// ---------------------------------------------------------------------------
// softmax over routes per class (coalesced [c][r] layout)
// ---------------------------------------------------------------------------
__global__ void __launch_bounds__(256) k_softmax() {
    int c = blockIdx.x, t = threadIdx.x;
    __shared__ float red[8];

    float v[5];
    #pragma unroll
    for (int q = 0; q < 5; q++) {
        int r = t + q*256;
        v[q] = (r < RR) ? g_b[c*RR + r] : -1e30f;
    }
    float m = fmaxf(fmaxf(fmaxf(v[0], v[1]), fmaxf(v[2], v[3])), v[4]);
    #pragma unroll
    for (int off = 16; off; off >>= 1) m = fmaxf(m, __shfl_xor_sync(~0u, m, off));
    if ((t & 31) == 0) red[t >> 5] = m;
    __syncthreads();
    m = red[0];
    #pragma unroll
    for (int q = 1; q < 8; q++) m = fmaxf(m, red[q]);

    float e[5], sum = 0.0f;
    #pragma unroll
    for (int q = 0; q < 5; q++) {
        int r = t + q*256;
        e[q] = (r < RR) ? __expf(v[q] - m) : 0.0f;
        sum += e[q];
    }
    #pragma unroll
    for (int off = 16; off; off >>= 1) sum += __shfl_xor_sync(~0u, sum, off);
    __syncthreads();
    if ((t & 31) == 0) red[t >> 5] = sum;
    __syncthreads();
    sum = 0.0f;
    #pragma unroll
    for (int q = 0; q < 8; q++) sum += red[q];
    float inv = 1.0f / sum;

    #pragma unroll
    for (int q = 0; q < 5; q++) {
        int r = t + q*256;
        if (r < RR) g_c[c*RR + r] = e[q] * inv;
    }
}

// ---------------------------------------------------------------------------
extern "C" void kernel_launch(void* const* d_in, const int* in_sizes, int n_in,
                              void* d_out, int out_size) {
    const float* x = (const float*)d_in[0];
    const float* W = (const float*)d_in[1];
    if (in_sizes[0] == RR*CC*OO*II && in_sizes[1] == BB*RR*II) {
        W = (const float*)d_in[0];
        x = (const float*)d_in[1];
    }
    float* out = (float*)d_out;

    k_prep<<<dim3(144, 4), 256>>>(x);
    for (int it = 0; it < NITER; it++) {
        k_spart<<<dim3(KSPLIT, 2), 256>>>(W);
        k_sqreduce<<<40, 256>>>(out, it == NITER - 1 ? 1 : 0);
        if (it < NITER - 1) {
            k_agree<<<144, 256>>>(W);
            k_softmax<<<CC, 256>>>();
        }
    }
}